// round 4
// baseline (speedup 1.0000x reference)
#include <cuda_runtime.h>
#include <cuda_bf16.h>
#include <math.h>

#define BETA 0.1f
#define MAX_B 16384

// Per-row results scratch (no device allocation allowed).
__device__ float g_row[MAX_B];

__device__ __forceinline__ float4 ldcs4(const float4* p) {
    return __ldcs(p);   // evict-first: action is touched exactly once
}

// One warp per row; each float4 load is exactly one size-4 group.
template <int GROUPS>
__global__ void policy_row_fixed(const float4* __restrict__ action,
                                 const float* __restrict__ reward,
                                 int B) {
    int warp = (blockIdx.x * blockDim.x + threadIdx.x) >> 5;
    if (warp >= B) return;
    int lane = threadIdx.x & 31;

    const float4* p = action + (size_t)warp * GROUPS + lane;

    float s = 0.0f;
    #pragma unroll 8
    for (int j = 0; j < GROUPS / 32; ++j) {
        float4 v = ldcs4(p + j * 32);
        s += fmaxf(fmaxf(v.x, v.y), fmaxf(v.z, v.w));
    }

    #pragma unroll
    for (int o = 16; o > 0; o >>= 1)
        s += __shfl_xor_sync(0xFFFFFFFFu, s, o);

    if (lane == 0) {
        float a_n = s * (1.0f / (float)GROUPS);
        float lg  = logf(a_n) * a_n;
        g_row[warp] = lg * (reward[warp] + BETA);
    }
}

// Generic fallback for other shapes.
__global__ void policy_row_generic(const float4* __restrict__ action,
                                   const float* __restrict__ reward,
                                   int groups_per_row, int B) {
    int warp = (blockIdx.x * blockDim.x + threadIdx.x) >> 5;
    if (warp >= B) return;
    int lane = threadIdx.x & 31;

    const float4* p = action + (size_t)warp * groups_per_row;

    float s = 0.0f;
    for (int j = lane; j < groups_per_row; j += 32) {
        float4 v = ldcs4(p + j);
        s += fmaxf(fmaxf(v.x, v.y), fmaxf(v.z, v.w));
    }

    #pragma unroll
    for (int o = 16; o > 0; o >>= 1)
        s += __shfl_xor_sync(0xFFFFFFFFu, s, o);

    if (lane == 0) {
        float a_n = s / (float)groups_per_row;
        float lg  = logf(a_n) * a_n;
        g_row[warp] = lg * (reward[warp] + BETA);
    }
}

// Single-block final reduce in double, write |mean| to out[0].
__global__ void policy_final_kernel(float* __restrict__ out, int B) {
    __shared__ double sm[256];
    double s = 0.0;
    for (int i = threadIdx.x; i < B; i += 256)
        s += (double)g_row[i];
    sm[threadIdx.x] = s;
    __syncthreads();
    #pragma unroll
    for (int o = 128; o > 0; o >>= 1) {
        if (threadIdx.x < o) sm[threadIdx.x] += sm[threadIdx.x + o];
        __syncthreads();
    }
    if (threadIdx.x == 0)
        out[0] = (float)fabs(sm[0] / (double)B);
}

extern "C" void kernel_launch(void* const* d_in, const int* in_sizes, int n_in,
                              void* d_out, int out_size) {
    // metadata order: q_eval [B,1], reward [B], action [B, 4*m]
    const float* reward  = (const float*)d_in[1];
    const float4* action = (const float4*)d_in[2];
    float* out = (float*)d_out;

    int B  = in_sizes[1];                 // 16384
    int a4 = in_sizes[2] / B;             // 8192 floats per row
    int groups = a4 / 4;                  // 2048 float4 groups per row

    int blocks = (B + 7) / 8;             // 8 warps (rows) per 256-thread block
    if (groups == 2048) {
        policy_row_fixed<2048><<<blocks, 256>>>(action, reward, B);
    } else {
        policy_row_generic<<<blocks, 256>>>(action, reward, groups, B);
    }
    policy_final_kernel<<<1, 256>>>(out, B);
}

// round 5
// speedup vs baseline: 1.0943x; 1.0943x over previous
#include <cuda_runtime.h>
#include <cuda_bf16.h>
#include <math.h>

#define BETA 0.1f
#define MAX_BLOCKS 4096   // covers B up to 32768 at 8 rows/block

// Scratch (no device allocation allowed).
__device__ double g_part[MAX_BLOCKS];
__device__ unsigned int g_count;   // zero-initialized; last block resets it

__device__ __forceinline__ float4 ldcs4(const float4* p) {
    return __ldcs(p);   // evict-first: action is touched exactly once
}

// One warp per row, 8 rows per block; last block folds the partials.
template <int GROUPS>
__global__ void policy_fused(const float4* __restrict__ action,
                             const float* __restrict__ reward,
                             float* __restrict__ out,
                             int B, int nblocks) {
    __shared__ float  srow[8];
    __shared__ bool   is_last;
    __shared__ double sred[256];

    int wid  = threadIdx.x >> 5;
    int lane = threadIdx.x & 31;
    int row  = blockIdx.x * 8 + wid;

    float s = 0.0f;
    if (row < B) {
        const float4* p = action + (size_t)row * GROUPS + lane;
        #pragma unroll 8
        for (int j = 0; j < GROUPS / 32; ++j) {
            float4 v = ldcs4(p + j * 32);
            s += fmaxf(fmaxf(v.x, v.y), fmaxf(v.z, v.w));
        }
        #pragma unroll
        for (int o = 16; o > 0; o >>= 1)
            s += __shfl_xor_sync(0xFFFFFFFFu, s, o);
        if (lane == 0) {
            float a_n = s * (1.0f / (float)GROUPS);
            float lg  = logf(a_n) * a_n;             // log(a_n)*a_n
            srow[wid] = lg * (reward[row] + BETA);   // (A + Bt) contribution
        }
    } else if (lane == 0) {
        srow[wid] = 0.0f;
    }
    __syncthreads();

    // Block partial: fixed-order sum of 8 rows in double.
    if (threadIdx.x == 0) {
        double ps = 0.0;
        #pragma unroll
        for (int i = 0; i < 8; ++i) ps += (double)srow[i];
        g_part[blockIdx.x] = ps;
        __threadfence();
        unsigned int old = atomicAdd(&g_count, 1u);
        is_last = (old == (unsigned int)nblocks - 1u);
    }
    __syncthreads();

    if (is_last) {
        // Fold all partials (warm in L2). Fixed order -> deterministic.
        double t = 0.0;
        for (int i = threadIdx.x; i < nblocks; i += 256)
            t += g_part[i];
        sred[threadIdx.x] = t;
        __syncthreads();
        #pragma unroll
        for (int o = 128; o > 0; o >>= 1) {
            if (threadIdx.x < o) sred[threadIdx.x] += sred[threadIdx.x + o];
            __syncthreads();
        }
        if (threadIdx.x == 0) {
            out[0] = (float)fabs(sred[0] / (double)B);
            g_count = 0;   // reset for next graph replay (deterministic)
        }
    }
}

// Generic fallback for other shapes (same structure, runtime group count).
__global__ void policy_fused_generic(const float4* __restrict__ action,
                                     const float* __restrict__ reward,
                                     float* __restrict__ out,
                                     int groups, int B, int nblocks) {
    __shared__ float  srow[8];
    __shared__ bool   is_last;
    __shared__ double sred[256];

    int wid  = threadIdx.x >> 5;
    int lane = threadIdx.x & 31;
    int row  = blockIdx.x * 8 + wid;

    float s = 0.0f;
    if (row < B) {
        const float4* p = action + (size_t)row * groups;
        for (int j = lane; j < groups; j += 32) {
            float4 v = ldcs4(p + j);
            s += fmaxf(fmaxf(v.x, v.y), fmaxf(v.z, v.w));
        }
        #pragma unroll
        for (int o = 16; o > 0; o >>= 1)
            s += __shfl_xor_sync(0xFFFFFFFFu, s, o);
        if (lane == 0) {
            float a_n = s / (float)groups;
            float lg  = logf(a_n) * a_n;
            srow[wid] = lg * (reward[row] + BETA);
        }
    } else if (lane == 0) {
        srow[wid] = 0.0f;
    }
    __syncthreads();

    if (threadIdx.x == 0) {
        double ps = 0.0;
        #pragma unroll
        for (int i = 0; i < 8; ++i) ps += (double)srow[i];
        g_part[blockIdx.x] = ps;
        __threadfence();
        unsigned int old = atomicAdd(&g_count, 1u);
        is_last = (old == (unsigned int)nblocks - 1u);
    }
    __syncthreads();

    if (is_last) {
        double t = 0.0;
        for (int i = threadIdx.x; i < nblocks; i += 256)
            t += g_part[i];
        sred[threadIdx.x] = t;
        __syncthreads();
        #pragma unroll
        for (int o = 128; o > 0; o >>= 1) {
            if (threadIdx.x < o) sred[threadIdx.x] += sred[threadIdx.x + o];
            __syncthreads();
        }
        if (threadIdx.x == 0) {
            out[0] = (float)fabs(sred[0] / (double)B);
            g_count = 0;
        }
    }
}

extern "C" void kernel_launch(void* const* d_in, const int* in_sizes, int n_in,
                              void* d_out, int out_size) {
    // metadata order: q_eval [B,1], reward [B], action [B, 4*m]
    const float* reward  = (const float*)d_in[1];
    const float4* action = (const float4*)d_in[2];
    float* out = (float*)d_out;

    int B  = in_sizes[1];                 // 16384
    int a4 = in_sizes[2] / B;             // 8192 floats per row
    int groups = a4 / 4;                  // 2048 float4 groups per row

    int blocks = (B + 7) / 8;             // 8 warps (rows) per 256-thread block
    if (groups == 2048) {
        policy_fused<2048><<<blocks, 256>>>(action, reward, out, B, blocks);
    } else {
        policy_fused_generic<<<blocks, 256>>>(action, reward, out, groups, B, blocks);
    }
}

// round 6
// speedup vs baseline: 1.1915x; 1.0887x over previous
#include <cuda_runtime.h>
#include <cuda_bf16.h>
#include <math.h>

#define BETA 0.1f
#define MAX_BLOCKS 8192

// Scratch (no device allocation allowed).
__device__ double g_part[MAX_BLOCKS];
__device__ unsigned int g_count;   // zero-init; last block resets -> graph-replay safe

__device__ __forceinline__ float4 ldcs4(const float4* p) {
    return __ldcs(p);   // evict-first: action touched exactly once
}
__device__ __forceinline__ float gmax4(float4 v) {
    return fmaxf(fmaxf(v.x, v.y), fmaxf(v.z, v.w));
}

// 2 warps per row (half-row each), 4 rows per 256-thread block.
// Explicit 4-deep load batching to force MLP>=4 in SASS.
template <int GROUPS>
__global__ void policy_fused2(const float4* __restrict__ action,
                              const float* __restrict__ reward,
                              float* __restrict__ out,
                              int B, int nblocks) {
    constexpr int HALF = GROUPS / 2;          // groups per warp
    __shared__ float  sh[8];                  // per-warp half sums
    __shared__ bool   is_last;
    __shared__ double sred[256];

    int wid  = threadIdx.x >> 5;
    int lane = threadIdx.x & 31;
    int rloc = wid >> 1;                      // 0..3 row within block
    int h    = wid & 1;                       // half index
    int row  = blockIdx.x * 4 + rloc;

    float s = 0.0f;
    if (row < B) {
        const float4* p = action + (size_t)row * GROUPS + h * HALF + lane;
        #pragma unroll 2
        for (int j = 0; j < HALF / 128; ++j) {          // 8 outer iters
            float4 v0 = ldcs4(p + j * 128);
            float4 v1 = ldcs4(p + j * 128 + 32);
            float4 v2 = ldcs4(p + j * 128 + 64);
            float4 v3 = ldcs4(p + j * 128 + 96);
            s += gmax4(v0); s += gmax4(v1);
            s += gmax4(v2); s += gmax4(v3);
        }
        #pragma unroll
        for (int o = 16; o > 0; o >>= 1)
            s += __shfl_xor_sync(0xFFFFFFFFu, s, o);
    }
    if (lane == 0) sh[wid] = (row < B) ? s : 0.0f;
    __syncthreads();

    // Thread 0: combine halves, apply per-row nonlinearity, block partial.
    if (threadIdx.x == 0) {
        double ps = 0.0;
        #pragma unroll
        for (int r = 0; r < 4; ++r) {
            int rr = blockIdx.x * 4 + r;
            if (rr < B) {
                float ssum = sh[2 * r] + sh[2 * r + 1];
                float a_n  = ssum * (1.0f / (float)GROUPS);
                float lg   = logf(a_n) * a_n;
                ps += (double)(lg * (reward[rr] + BETA));
            }
        }
        g_part[blockIdx.x] = ps;
        __threadfence();
        unsigned int old = atomicAdd(&g_count, 1u);
        is_last = (old == (unsigned int)nblocks - 1u);
    }
    __syncthreads();

    if (is_last) {
        double t = 0.0;
        for (int i = threadIdx.x; i < nblocks; i += 256)
            t += g_part[i];
        sred[threadIdx.x] = t;
        __syncthreads();
        #pragma unroll
        for (int o = 128; o > 0; o >>= 1) {
            if (threadIdx.x < o) sred[threadIdx.x] += sred[threadIdx.x + o];
            __syncthreads();
        }
        if (threadIdx.x == 0) {
            out[0] = (float)fabs(sred[0] / (double)B);
            g_count = 0;   // reset for next graph replay
        }
    }
}

// Generic fallback: warp per row, 8 rows per block.
__global__ void policy_fused_generic(const float4* __restrict__ action,
                                     const float* __restrict__ reward,
                                     float* __restrict__ out,
                                     int groups, int B, int nblocks) {
    __shared__ float  srow[8];
    __shared__ bool   is_last;
    __shared__ double sred[256];

    int wid  = threadIdx.x >> 5;
    int lane = threadIdx.x & 31;
    int row  = blockIdx.x * 8 + wid;

    float s = 0.0f;
    if (row < B) {
        const float4* p = action + (size_t)row * groups;
        for (int j = lane; j < groups; j += 32)
            s += gmax4(ldcs4(p + j));
        #pragma unroll
        for (int o = 16; o > 0; o >>= 1)
            s += __shfl_xor_sync(0xFFFFFFFFu, s, o);
        if (lane == 0) {
            float a_n = s / (float)groups;
            float lg  = logf(a_n) * a_n;
            srow[wid] = lg * (reward[row] + BETA);
        }
    } else if (lane == 0) {
        srow[wid] = 0.0f;
    }
    __syncthreads();

    if (threadIdx.x == 0) {
        double ps = 0.0;
        #pragma unroll
        for (int i = 0; i < 8; ++i) ps += (double)srow[i];
        g_part[blockIdx.x] = ps;
        __threadfence();
        unsigned int old = atomicAdd(&g_count, 1u);
        is_last = (old == (unsigned int)nblocks - 1u);
    }
    __syncthreads();

    if (is_last) {
        double t = 0.0;
        for (int i = threadIdx.x; i < nblocks; i += 256)
            t += g_part[i];
        sred[threadIdx.x] = t;
        __syncthreads();
        #pragma unroll
        for (int o = 128; o > 0; o >>= 1) {
            if (threadIdx.x < o) sred[threadIdx.x] += sred[threadIdx.x + o];
            __syncthreads();
        }
        if (threadIdx.x == 0) {
            out[0] = (float)fabs(sred[0] / (double)B);
            g_count = 0;
        }
    }
}

extern "C" void kernel_launch(void* const* d_in, const int* in_sizes, int n_in,
                              void* d_out, int out_size) {
    // metadata order: q_eval [B,1], reward [B], action [B, 4*m]
    const float* reward  = (const float*)d_in[1];
    const float4* action = (const float4*)d_in[2];
    float* out = (float*)d_out;

    int B  = in_sizes[1];                 // 16384
    int a4 = in_sizes[2] / B;             // 8192 floats per row
    int groups = a4 / 4;                  // 2048 float4 groups per row

    if (groups == 2048) {
        int blocks = (B + 3) / 4;         // 4 rows per block, 2 warps/row
        policy_fused2<2048><<<blocks, 256>>>(action, reward, out, B, blocks);
    } else {
        int blocks = (B + 7) / 8;
        policy_fused_generic<<<blocks, 256>>>(action, reward, out, groups, B, blocks);
    }
}

// round 10
// speedup vs baseline: 1.2210x; 1.0248x over previous
#include <cuda_runtime.h>
#include <cuda_bf16.h>
#include <math.h>

#define BETA 0.1f
#define MAX_BLOCKS 8192

// Scratch (no device allocation allowed).
__device__ double g_part[MAX_BLOCKS];
__device__ unsigned int g_count;   // zero-init; last block resets -> graph-replay safe

__device__ __forceinline__ float4 ldcs4(const float4* p) {
    return __ldcs(p);   // evict-first: action touched exactly once
}
__device__ __forceinline__ float gmax4(float4 v) {
    return fmaxf(fmaxf(v.x, v.y), fmaxf(v.z, v.w));
}

// 2 warps per row (half-row each), 4 rows per 256-thread block.
// 8-deep explicit load batching to force MLP>=8 in SASS.
template <int GROUPS>
__global__ void policy_fused8(const float4* __restrict__ action,
                              const float* __restrict__ reward,
                              float* __restrict__ out,
                              int B, int nblocks) {
    constexpr int HALF = GROUPS / 2;          // groups per warp (1024)
    __shared__ float  sh[8];                  // per-warp half sums
    __shared__ bool   is_last;
    __shared__ double sred[256];

    int wid  = threadIdx.x >> 5;
    int lane = threadIdx.x & 31;
    int rloc = wid >> 1;                      // 0..3 row within block
    int h    = wid & 1;                       // half index
    int row  = blockIdx.x * 4 + rloc;

    float s = 0.0f;
    if (row < B) {
        const float4* p = action + (size_t)row * GROUPS + h * HALF + lane;
        #pragma unroll
        for (int j = 0; j < HALF / 256; ++j) {   // 4 outer iters, 8 loads each
            float4 v0 = ldcs4(p + j * 256);
            float4 v1 = ldcs4(p + j * 256 + 32);
            float4 v2 = ldcs4(p + j * 256 + 64);
            float4 v3 = ldcs4(p + j * 256 + 96);
            float4 v4 = ldcs4(p + j * 256 + 128);
            float4 v5 = ldcs4(p + j * 256 + 160);
            float4 v6 = ldcs4(p + j * 256 + 192);
            float4 v7 = ldcs4(p + j * 256 + 224);
            s += gmax4(v0); s += gmax4(v1);
            s += gmax4(v2); s += gmax4(v3);
            s += gmax4(v4); s += gmax4(v5);
            s += gmax4(v6); s += gmax4(v7);
        }
        #pragma unroll
        for (int o = 16; o > 0; o >>= 1)
            s += __shfl_xor_sync(0xFFFFFFFFu, s, o);
    }
    if (lane == 0) sh[wid] = (row < B) ? s : 0.0f;
    __syncthreads();

    // Thread 0: combine halves, per-row nonlinearity, block partial.
    if (threadIdx.x == 0) {
        double ps = 0.0;
        #pragma unroll
        for (int r = 0; r < 4; ++r) {
            int rr = blockIdx.x * 4 + r;
            if (rr < B) {
                float ssum = sh[2 * r] + sh[2 * r + 1];
                float a_n  = ssum * (1.0f / (float)GROUPS);
                float lg   = logf(a_n) * a_n;
                ps += (double)(lg * (reward[rr] + BETA));
            }
        }
        g_part[blockIdx.x] = ps;
        __threadfence();
        unsigned int old = atomicAdd(&g_count, 1u);
        is_last = (old == (unsigned int)nblocks - 1u);
    }
    __syncthreads();

    if (is_last) {
        double t = 0.0;
        for (int i = threadIdx.x; i < nblocks; i += 256)
            t += g_part[i];
        sred[threadIdx.x] = t;
        __syncthreads();
        #pragma unroll
        for (int o = 128; o > 0; o >>= 1) {
            if (threadIdx.x < o) sred[threadIdx.x] += sred[threadIdx.x + o];
            __syncthreads();
        }
        if (threadIdx.x == 0) {
            out[0] = (float)fabs(sred[0] / (double)B);
            g_count = 0;   // reset for next graph replay
        }
    }
}

// Generic fallback: warp per row, 8 rows per block.
__global__ void policy_fused_generic(const float4* __restrict__ action,
                                     const float* __restrict__ reward,
                                     float* __restrict__ out,
                                     int groups, int B, int nblocks) {
    __shared__ float  srow[8];
    __shared__ bool   is_last;
    __shared__ double sred[256];

    int wid  = threadIdx.x >> 5;
    int lane = threadIdx.x & 31;
    int row  = blockIdx.x * 8 + wid;

    float s = 0.0f;
    if (row < B) {
        const float4* p = action + (size_t)row * groups;
        for (int j = lane; j < groups; j += 32)
            s += gmax4(ldcs4(p + j));
        #pragma unroll
        for (int o = 16; o > 0; o >>= 1)
            s += __shfl_xor_sync(0xFFFFFFFFu, s, o);
        if (lane == 0) {
            float a_n = s / (float)groups;
            float lg  = logf(a_n) * a_n;
            srow[wid] = lg * (reward[row] + BETA);
        }
    } else if (lane == 0) {
        srow[wid] = 0.0f;
    }
    __syncthreads();

    if (threadIdx.x == 0) {
        double ps = 0.0;
        #pragma unroll
        for (int i = 0; i < 8; ++i) ps += (double)srow[i];
        g_part[blockIdx.x] = ps;
        __threadfence();
        unsigned int old = atomicAdd(&g_count, 1u);
        is_last = (old == (unsigned int)nblocks - 1u);
    }
    __syncthreads();

    if (is_last) {
        double t = 0.0;
        for (int i = threadIdx.x; i < nblocks; i += 256)
            t += g_part[i];
        sred[threadIdx.x] = t;
        __syncthreads();
        #pragma unroll
        for (int o = 128; o > 0; o >>= 1) {
            if (threadIdx.x < o) sred[threadIdx.x] += sred[threadIdx.x + o];
            __syncthreads();
        }
        if (threadIdx.x == 0) {
            out[0] = (float)fabs(sred[0] / (double)B);
            g_count = 0;
        }
    }
}

extern "C" void kernel_launch(void* const* d_in, const int* in_sizes, int n_in,
                              void* d_out, int out_size) {
    // metadata order: q_eval [B,1], reward [B], action [B, 4*m]
    const float* reward  = (const float*)d_in[1];
    const float4* action = (const float4*)d_in[2];
    float* out = (float*)d_out;

    int B  = in_sizes[1];                 // 16384
    int a4 = in_sizes[2] / B;             // 8192 floats per row
    int groups = a4 / 4;                  // 2048 float4 groups per row

    if (groups == 2048) {
        int blocks = (B + 3) / 4;         // 4 rows per block, 2 warps/row
        policy_fused8<2048><<<blocks, 256>>>(action, reward, out, B, blocks);
    } else {
        int blocks = (B + 7) / 8;
        policy_fused_generic<<<blocks, 256>>>(action, reward, out, groups, B, blocks);
    }
}